// round 16
// baseline (speedup 1.0000x reference)
#include <cuda_runtime.h>
#include <cuda_bf16.h>
#include <stdint.h>

#define BATCH 16
#define CDIM 256
#define HW 4096
#define KC 32                  // k per chunk (fp32 elems) = two k16 MMA steps
#define KSPLIT 8
#define KSEG (HW / KSPLIT)     // 512
#define NKCS (KSEG / KC)       // 16 chunks
#define SSTR 40                // bf16 smem row stride (80B; conflict-free ldsm)
#define TAU 8.0f

// dynamic smem layout (bytes):
// fp32 ring: 2 stages x (A 16KB + B 16KB)   [0, 65536)
// bf16 A double buffer: 2 x 10240           [65536, 86016)
// bf16 B double buffer: 2 x 10240           [86016, 106496)
#define F32A(s) ((s) * 32768)
#define F32B(s) ((s) * 32768 + 16384)
#define BFA(p) (65536 + (p) * 10240)
#define BFB(p) (86016 + (p) * 10240)
#define SMEM_BYTES 106496

__device__ __nv_bfloat16 g_part[KSPLIT][BATCH * CDIM * CDIM];   // 16 MB dot partials
__device__ float g_ynp[KSPLIT][BATCH * CDIM];                   // |y|^2 partials (fp32)

// ---------------- helpers ----------------
__device__ __forceinline__ uint32_t bf2(float x, float y) {
    __nv_bfloat162 h = __floats2bfloat162_rn(x, y);
    return *reinterpret_cast<uint32_t*>(&h);
}
__device__ __forceinline__ uint32_t smaddr(const void* p) {
    return (uint32_t)__cvta_generic_to_shared(p);
}
__device__ __forceinline__ void cpasync16(uint32_t dst, const float* src) {
    asm volatile("cp.async.cg.shared.global [%0], [%1], 16;" :: "r"(dst), "l"(src));
}
__device__ __forceinline__ void cp_commit() {
    asm volatile("cp.async.commit_group;" ::: "memory");
}
__device__ __forceinline__ void cp_wait0() {
    asm volatile("cp.async.wait_group 0;" ::: "memory");
}
__device__ __forceinline__ void cp_wait1() {
    asm volatile("cp.async.wait_group 1;" ::: "memory");
}
__device__ __forceinline__ void ldsm4(uint32_t a, uint32_t* r) {
    asm volatile("ldmatrix.sync.aligned.m8n8.x4.shared.b16 {%0,%1,%2,%3}, [%4];"
                 : "=r"(r[0]), "=r"(r[1]), "=r"(r[2]), "=r"(r[3]) : "r"(a));
}
__device__ __forceinline__ void mma_bf16(float* d, const uint32_t* a, const uint32_t* b) {
    asm volatile("mma.sync.aligned.m16n8k16.row.col.f32.bf16.bf16.f32 "
                 "{%0,%1,%2,%3}, {%4,%5,%6,%7}, {%8,%9}, {%0,%1,%2,%3};"
                 : "+f"(d[0]), "+f"(d[1]), "+f"(d[2]), "+f"(d[3])
                 : "r"(a[0]), "r"(a[1]), "r"(a[2]), "r"(a[3]), "r"(b[0]), "r"(b[1]));
}

// ---------------------------------------------------------------------------
// 1) dot partials over one k-segment. Pipeline offset: at iter kc we convert
//    chunk kc+1 (fp32 -> bf16) WHILE consuming bf16 tile kc — LDS/STS overlap
//    ldsm/MMA instead of serializing behind a barrier.
//    CTA 128(i) x 128(j), 512 threads, 16 warps 4(i)x4(j), warp tile 32x32.
// ---------------------------------------------------------------------------
__global__ void __launch_bounds__(512, 2) gemm_kernel(const float* __restrict__ X,
                                                      const float* __restrict__ Y) {
    extern __shared__ __align__(16) uint8_t sm[];
    const uint32_t smu = smaddr(sm);

    const int t  = threadIdx.x;
    const int b  = blockIdx.z >> 3;
    const int ks = blockIdx.z & 7;
    const int i0 = blockIdx.y * 128;
    const int j0 = blockIdx.x * 128;

    // loader: o = 16B segment (0..7) of the 128B k32 row; rows tr and tr+64
    const int o  = t & 7;
    const int tr = t >> 3;    // 0..63
    const float* aSrc = X + (size_t)(b * CDIM + i0 + tr) * HW + ks * KSEG + o * 4;
    const float* bSrc = Y + (size_t)(b * CDIM + j0 + tr) * HW + ks * KSEG + o * 4;
    const uint32_t f0 = (uint32_t)tr * 128u + (uint32_t)o * 16u;   // within fp32 stage
    const uint32_t g0 = 2u * ((uint32_t)tr * SSTR) + (uint32_t)o * 8u;  // bf16 byte off
    const size_t ROW64 = (size_t)64 * HW;

    // consumer fragment mapping (R7/R12-verified)
    const int lane = t & 31;
    const int w    = t >> 5;
    const int i0w  = (w >> 2) * 32;
    const int j0w  = (w & 3) * 32;
    const uint32_t aoff = 2u * ((uint32_t)(i0w + (lane & 15)) * SSTR + (uint32_t)((lane >> 4) * 8));
    const uint32_t boff = 2u * ((uint32_t)(j0w + (lane & 7) + ((lane >> 4) << 3)) * SSTR
                                + (uint32_t)(((lane >> 3) & 1) * 8));

    const bool doYn = (blockIdx.y == 0);
    float ysq0 = 0.f, ysq1 = 0.f;

    float acc[2][4][4];
#pragma unroll
    for (int m = 0; m < 2; ++m)
#pragma unroll
        for (int n = 0; n < 4; ++n)
#pragma unroll
            for (int e = 0; e < 4; ++e) acc[m][n][e] = 0.f;

    // cvt helper (as lambda to keep code compact): chunk c, stage/tile = c&1
    auto cvt_chunk = [&](int c) {
        const int s = c & 1;
        float4 va0 = *(const float4*)((const float*)(sm + F32A(s) + f0));
        float4 va1 = *(const float4*)((const float*)(sm + F32A(s) + f0 + 8192u));
        float4 vb0 = *(const float4*)((const float*)(sm + F32B(s) + f0));
        float4 vb1 = *(const float4*)((const float*)(sm + F32B(s) + f0 + 8192u));
        if (doYn) {
            ysq0 += vb0.x * vb0.x + vb0.y * vb0.y + vb0.z * vb0.z + vb0.w * vb0.w;
            ysq1 += vb1.x * vb1.x + vb1.y * vb1.y + vb1.z * vb1.z + vb1.w * vb1.w;
        }
        *(uint2*)(sm + BFA(s) + g0)         = make_uint2(bf2(va0.x, va0.y), bf2(va0.z, va0.w));
        *(uint2*)(sm + BFA(s) + g0 + 5120u) = make_uint2(bf2(va1.x, va1.y), bf2(va1.z, va1.w));
        *(uint2*)(sm + BFB(s) + g0)         = make_uint2(bf2(vb0.x, vb0.y), bf2(vb0.z, vb0.w));
        *(uint2*)(sm + BFB(s) + g0 + 5120u) = make_uint2(bf2(vb1.x, vb1.y), bf2(vb1.z, vb1.w));
    };

    // prologue: prefetch chunks 0,1; convert chunk 0
#pragma unroll
    for (int pc = 0; pc < 2; ++pc) {
        cpasync16(smu + F32A(pc) + f0, aSrc + pc * KC);
        cpasync16(smu + F32A(pc) + f0 + 8192u, aSrc + ROW64 + pc * KC);
        cpasync16(smu + F32B(pc) + f0, bSrc + pc * KC);
        cpasync16(smu + F32B(pc) + f0 + 8192u, bSrc + ROW64 + pc * KC);
        cp_commit();
    }
    cp_wait1();      // chunk 0 landed (own data)
    cvt_chunk(0);    // -> bf16 tile 0

    for (int kc = 0; kc < NKCS; ++kc) {
        const int s = kc & 1;

        // one barrier per chunk: tile kc (cvt'd last iter) visible to all;
        // last iter's ldsm on tile (kc+1)&1 done before this iter's STS to it
        __syncthreads();

        // convert chunk kc+1 (overlaps with the MMA below in the same iter)
        if (kc + 1 < NKCS) {
            cp_wait0();        // chunk kc+1 landed (own-data readback only)
            cvt_chunk(kc + 1); // -> bf16 tile (kc+1)&1
        }

        // refill stage s (this thread's own slot; it read it back last iter)
        if (kc + 2 < NKCS) {
            cpasync16(smu + F32A(s) + f0, aSrc + (kc + 2) * KC);
            cpasync16(smu + F32A(s) + f0 + 8192u, aSrc + ROW64 + (kc + 2) * KC);
            cpasync16(smu + F32B(s) + f0, bSrc + (kc + 2) * KC);
            cpasync16(smu + F32B(s) + f0 + 8192u, bSrc + ROW64 + (kc + 2) * KC);
        }
        cp_commit();   // uniform: one group per iteration

        // consume tile kc: two k16 steps (8 ldsm.x4 + 16 MMA)
#pragma unroll
        for (int st = 0; st < 2; ++st) {
            const uint32_t ko = (uint32_t)st * 32u;   // 16 bf16 = 32B
            uint32_t ah0[4], ah1[4], bh0[4], bh1[4];
            ldsm4(smu + BFA(s) + aoff + ko, ah0);
            ldsm4(smu + BFA(s) + aoff + ko + 2u * 16 * SSTR, ah1);
            ldsm4(smu + BFB(s) + boff + ko, bh0);
            ldsm4(smu + BFB(s) + boff + ko + 2u * 16 * SSTR, bh1);
            mma_bf16(acc[0][0], ah0, bh0);
            mma_bf16(acc[0][1], ah0, bh0 + 2);
            mma_bf16(acc[0][2], ah0, bh1);
            mma_bf16(acc[0][3], ah0, bh1 + 2);
            mma_bf16(acc[1][0], ah1, bh0);
            mma_bf16(acc[1][1], ah1, bh0 + 2);
            mma_bf16(acc[1][2], ah1, bh1);
            mma_bf16(acc[1][3], ah1, bh1 + 2);
        }
    }

    if (doYn) {        // |y|^2 partials (exact fp32): 8 lanes per row
        ysq0 += __shfl_xor_sync(0xffffffffu, ysq0, 1);
        ysq0 += __shfl_xor_sync(0xffffffffu, ysq0, 2);
        ysq0 += __shfl_xor_sync(0xffffffffu, ysq0, 4);
        ysq1 += __shfl_xor_sync(0xffffffffu, ysq1, 1);
        ysq1 += __shfl_xor_sync(0xffffffffu, ysq1, 2);
        ysq1 += __shfl_xor_sync(0xffffffffu, ysq1, 4);
        if (o == 0) {
            g_ynp[ks][b * CDIM + j0 + tr]      = ysq0;
            g_ynp[ks][b * CDIM + j0 + tr + 64] = ysq1;
        }
    }

    // epilogue: store dot partials as packed bf16 pairs
    const int gr = lane >> 2, gc = lane & 3;
    __nv_bfloat16* gout = g_part[ks];
#pragma unroll
    for (int mi = 0; mi < 2; ++mi) {
#pragma unroll
        for (int nb = 0; nb < 4; ++nb) {
            const int jc = j0w + nb * 8 + gc * 2;
            const int grow = b * CDIM + i0 + i0w + mi * 16 + gr;
            *(uint32_t*)&gout[(size_t)grow * CDIM + j0 + jc] =
                bf2(acc[mi][nb][0], acc[mi][nb][1]);
            *(uint32_t*)&gout[(size_t)(grow + 8) * CDIM + j0 + jc] =
                bf2(acc[mi][nb][2], acc[mi][nb][3]);
        }
    }
}

// ---------------------------------------------------------------------------
// 2) fused: argmin of (yn[j] - 2*dot) + exact-fp32 rescue + row gather.
//    One block per output row.
// ---------------------------------------------------------------------------
__global__ void __launch_bounds__(256) rescore_gather_kernel(const float* __restrict__ X,
                                                             const float* __restrict__ Y,
                                                             float* __restrict__ out) {
    const int row = blockIdx.x;           // b*CDIM + i
    const int b   = row >> 8;
    const int t   = threadIdx.x;

    __shared__ float s_red[8];
    __shared__ float s_minv;
    __shared__ int   s_cnt;
    __shared__ int   s_lst[256];
    __shared__ int   s_bestj;

    const size_t off = (size_t)row * CDIM + t;
    float dot = 0.f, yn = 0.f;
#pragma unroll
    for (int k = 0; k < KSPLIT; ++k) {
        dot += __bfloat162float(g_part[k][off]);
        yn  += g_ynp[k][b * CDIM + t];
    }
    float d = yn - 2.f * dot;

    float vv = d;
#pragma unroll
    for (int o = 16; o; o >>= 1) vv = fminf(vv, __shfl_down_sync(0xffffffffu, vv, o));
    if ((t & 31) == 0) s_red[t >> 5] = vv;
    __syncthreads();
    if (t == 0) {
        float m = s_red[0];
#pragma unroll
        for (int i = 1; i < 8; ++i) m = fminf(m, s_red[i]);
        s_minv = m;
        s_cnt = 0;
    }
    __syncthreads();

    if (d <= s_minv + TAU) {
        int pos = atomicAdd(&s_cnt, 1);
        s_lst[pos] = t;
    }
    __syncthreads();

    const int n = s_cnt;
    if (n == 1) {
        if (t == 0) s_bestj = s_lst[0];
    } else {
        // exact fp32 rescore; tie -> lower j
        const float* xr = X + (size_t)row * HW;
        float bestv = 3.4e38f;
        int   bestj = 0x7fffffff;
        for (int c = 0; c < n; ++c) {
            const int j = s_lst[c];
            const float* yr = Y + (size_t)(b * CDIM + j) * HW;
            float s = 0.f;
#pragma unroll
            for (int q = 0; q < 4; ++q) {
                float4 xv = ((const float4*)xr)[t + q * 256];
                float4 yv = ((const float4*)yr)[t + q * 256];
                float dx = xv.x - yv.x, dy = xv.y - yv.y, dz = xv.z - yv.z, dw = xv.w - yv.w;
                s += dx * dx + dy * dy + dz * dz + dw * dw;
            }
#pragma unroll
            for (int o = 16; o; o >>= 1) s += __shfl_down_sync(0xffffffffu, s, o);
            if ((t & 31) == 0) s_red[t >> 5] = s;
            __syncthreads();
            if (t == 0) {
                float tot = 0.f;
#pragma unroll
                for (int i = 0; i < 8; ++i) tot += s_red[i];
                if (tot < bestv || (tot == bestv && j < bestj)) { bestv = tot; bestj = j; }
            }
            __syncthreads();
        }
        if (t == 0) s_bestj = bestj;
    }
    __syncthreads();

    // gather: copy Y[b, bestj, :] -> out[row, :]  (1024 float4, 4 per thread)
    const float4* yp = (const float4*)(Y + (size_t)(b * CDIM + s_bestj) * HW);
    float4*       op = (float4*)(out + (size_t)row * HW);
#pragma unroll
    for (int q = 0; q < 4; ++q)
        op[t + q * 256] = yp[t + q * 256];
}

// ---------------------------------------------------------------------------
extern "C" void kernel_launch(void* const* d_in, const int* in_sizes, int n_in,
                              void* d_out, int out_size) {
    const float* x = (const float*)d_in[0];
    const float* y = (const float*)d_in[1];
    float* out = (float*)d_out;

    cudaFuncSetAttribute(gemm_kernel,
                         cudaFuncAttributeMaxDynamicSharedMemorySize, SMEM_BYTES);

    dim3 g(CDIM / 128, CDIM / 128, BATCH * KSPLIT);   // 2 x 2 x 128 = 512 CTAs
    gemm_kernel<<<g, 512, SMEM_BYTES>>>(x, y);

    rescore_gather_kernel<<<BATCH * CDIM, 256>>>(x, y, out);
}

// round 17
// speedup vs baseline: 1.0311x; 1.0311x over previous
#include <cuda_runtime.h>
#include <cuda_bf16.h>
#include <stdint.h>

#define BATCH 16
#define CDIM 256
#define HW 4096
#define KC 32                  // k per chunk (fp32 elems) = two k16 MMA steps
#define KSPLIT 8
#define KSEG (HW / KSPLIT)     // 512
#define NKCS (KSEG / KC)       // 16 chunks
#define SSTR 40                // bf16 smem row stride (80B; conflict-free ldsm)
#define TAU 8.0f

// dynamic smem layout (bytes):
// fp32 ring: 2 stages x (A 16KB + B 16KB)   [0, 65536)
// bf16 A double buffer: 2 x 10240           [65536, 86016)
// bf16 B double buffer: 2 x 10240           [86016, 106496)
#define F32A(s) ((s) * 32768)
#define F32B(s) ((s) * 32768 + 16384)
#define BFA(p) (65536 + (p) * 10240)
#define BFB(p) (86016 + (p) * 10240)
#define SMEM_BYTES 106496

__device__ __nv_bfloat16 g_part[KSPLIT][BATCH * CDIM * CDIM];   // 16 MB dot partials
__device__ float g_ynp[KSPLIT][BATCH * CDIM];                   // |y|^2 partials (fp32)

// ---------------- helpers ----------------
__device__ __forceinline__ uint32_t bf2(float x, float y) {
    __nv_bfloat162 h = __floats2bfloat162_rn(x, y);
    return *reinterpret_cast<uint32_t*>(&h);
}
__device__ __forceinline__ uint32_t smaddr(const void* p) {
    return (uint32_t)__cvta_generic_to_shared(p);
}
__device__ __forceinline__ void cpasync16(uint32_t dst, const float* src) {
    asm volatile("cp.async.cg.shared.global [%0], [%1], 16;" :: "r"(dst), "l"(src));
}
__device__ __forceinline__ void cp_commit() {
    asm volatile("cp.async.commit_group;" ::: "memory");
}
__device__ __forceinline__ void cp_wait1() {
    asm volatile("cp.async.wait_group 1;" ::: "memory");
}
__device__ __forceinline__ void ldsm4(uint32_t a, uint32_t* r) {
    asm volatile("ldmatrix.sync.aligned.m8n8.x4.shared.b16 {%0,%1,%2,%3}, [%4];"
                 : "=r"(r[0]), "=r"(r[1]), "=r"(r[2]), "=r"(r[3]) : "r"(a));
}
__device__ __forceinline__ void mma_bf16(float* d, const uint32_t* a, const uint32_t* b) {
    asm volatile("mma.sync.aligned.m16n8k16.row.col.f32.bf16.bf16.f32 "
                 "{%0,%1,%2,%3}, {%4,%5,%6,%7}, {%8,%9}, {%0,%1,%2,%3};"
                 : "+f"(d[0]), "+f"(d[1]), "+f"(d[2]), "+f"(d[3])
                 : "r"(a[0]), "r"(a[1]), "r"(a[2]), "r"(a[3]), "r"(b[0]), "r"(b[1]));
}

// ---------------------------------------------------------------------------
// 1) dot partials over one k-segment. cp.async fp32 ring (2 stages, k32) ->
//    in-smem cvt to bf16 (double buffer) -> ldsm + m16n8k16 bf16 MMA.
//    (R14 structure — best measured.) Epilogue uses streaming stores so the
//    partial matrices don't evict Y from L2.
// ---------------------------------------------------------------------------
__global__ void __launch_bounds__(512, 2) gemm_kernel(const float* __restrict__ X,
                                                      const float* __restrict__ Y) {
    extern __shared__ __align__(16) uint8_t sm[];
    const uint32_t smu = smaddr(sm);

    const int t  = threadIdx.x;
    const int b  = blockIdx.z >> 3;
    const int ks = blockIdx.z & 7;
    const int i0 = blockIdx.y * 128;
    const int j0 = blockIdx.x * 128;

    // loader: o = 16B segment (0..7) of the 128B k32 row; rows tr and tr+64
    const int o  = t & 7;
    const int tr = t >> 3;    // 0..63
    const float* aSrc = X + (size_t)(b * CDIM + i0 + tr) * HW + ks * KSEG + o * 4;
    const float* bSrc = Y + (size_t)(b * CDIM + j0 + tr) * HW + ks * KSEG + o * 4;
    const uint32_t f0 = (uint32_t)tr * 128u + (uint32_t)o * 16u;   // within fp32 stage
    const uint32_t g0 = 2u * ((uint32_t)tr * SSTR) + (uint32_t)o * 8u;  // bf16 byte off
    const size_t ROW64 = (size_t)64 * HW;

    // consumer fragment mapping (R7/R12-verified)
    const int lane = t & 31;
    const int w    = t >> 5;
    const int i0w  = (w >> 2) * 32;
    const int j0w  = (w & 3) * 32;
    const uint32_t aoff = 2u * ((uint32_t)(i0w + (lane & 15)) * SSTR + (uint32_t)((lane >> 4) * 8));
    const uint32_t boff = 2u * ((uint32_t)(j0w + (lane & 7) + ((lane >> 4) << 3)) * SSTR
                                + (uint32_t)(((lane >> 3) & 1) * 8));

    const bool doYn = (blockIdx.y == 0);
    float ysq0 = 0.f, ysq1 = 0.f;

    float acc[2][4][4];
#pragma unroll
    for (int m = 0; m < 2; ++m)
#pragma unroll
        for (int n = 0; n < 4; ++n)
#pragma unroll
            for (int e = 0; e < 4; ++e) acc[m][n][e] = 0.f;

    // prologue: prefetch chunks 0,1 into stages 0,1
#pragma unroll
    for (int pc = 0; pc < 2; ++pc) {
        cpasync16(smu + F32A(pc) + f0, aSrc + pc * KC);
        cpasync16(smu + F32A(pc) + f0 + 8192u, aSrc + ROW64 + pc * KC);
        cpasync16(smu + F32B(pc) + f0, bSrc + pc * KC);
        cpasync16(smu + F32B(pc) + f0 + 8192u, bSrc + ROW64 + pc * KC);
        cp_commit();
    }

    for (int kc = 0; kc < NKCS; ++kc) {
        const int s = kc & 1;

        cp_wait1();    // chunk kc landed (chunk kc+1 may still be in flight)

        // cvt: read back own 4 x 16B, convert, store to bf16 tile s
        float4 va0 = *(const float4*)((const float*)(sm + F32A(s) + f0));
        float4 va1 = *(const float4*)((const float*)(sm + F32A(s) + f0 + 8192u));
        float4 vb0 = *(const float4*)((const float*)(sm + F32B(s) + f0));
        float4 vb1 = *(const float4*)((const float*)(sm + F32B(s) + f0 + 8192u));
        if (doYn) {
            ysq0 += vb0.x * vb0.x + vb0.y * vb0.y + vb0.z * vb0.z + vb0.w * vb0.w;
            ysq1 += vb1.x * vb1.x + vb1.y * vb1.y + vb1.z * vb1.z + vb1.w * vb1.w;
        }
        *(uint2*)(sm + BFA(s) + g0)         = make_uint2(bf2(va0.x, va0.y), bf2(va0.z, va0.w));
        *(uint2*)(sm + BFA(s) + g0 + 5120u) = make_uint2(bf2(va1.x, va1.y), bf2(va1.z, va1.w));
        *(uint2*)(sm + BFB(s) + g0)         = make_uint2(bf2(vb0.x, vb0.y), bf2(vb0.z, vb0.w));
        *(uint2*)(sm + BFB(s) + g0 + 5120u) = make_uint2(bf2(vb1.x, vb1.y), bf2(vb1.z, vb1.w));

        __syncthreads();   // bf16 tile s complete; fp32 stage s consumed by all

        // refill stage s with chunk kc+2
        if (kc + 2 < NKCS) {
            cpasync16(smu + F32A(s) + f0, aSrc + (kc + 2) * KC);
            cpasync16(smu + F32A(s) + f0 + 8192u, aSrc + ROW64 + (kc + 2) * KC);
            cpasync16(smu + F32B(s) + f0, bSrc + (kc + 2) * KC);
            cpasync16(smu + F32B(s) + f0 + 8192u, bSrc + ROW64 + (kc + 2) * KC);
        }
        cp_commit();   // uniform: one group per iteration

        // consume: two k16 steps (8 ldsm.x4 + 16 MMA)
#pragma unroll
        for (int st = 0; st < 2; ++st) {
            const uint32_t ko = (uint32_t)st * 32u;   // 16 bf16 = 32B
            uint32_t ah0[4], ah1[4], bh0[4], bh1[4];
            ldsm4(smu + BFA(s) + aoff + ko, ah0);
            ldsm4(smu + BFA(s) + aoff + ko + 2u * 16 * SSTR, ah1);
            ldsm4(smu + BFB(s) + boff + ko, bh0);
            ldsm4(smu + BFB(s) + boff + ko + 2u * 16 * SSTR, bh1);
            mma_bf16(acc[0][0], ah0, bh0);
            mma_bf16(acc[0][1], ah0, bh0 + 2);
            mma_bf16(acc[0][2], ah0, bh1);
            mma_bf16(acc[0][3], ah0, bh1 + 2);
            mma_bf16(acc[1][0], ah1, bh0);
            mma_bf16(acc[1][1], ah1, bh0 + 2);
            mma_bf16(acc[1][2], ah1, bh1);
            mma_bf16(acc[1][3], ah1, bh1 + 2);
        }
    }

    if (doYn) {        // |y|^2 partials (exact fp32): 8 lanes per row
        ysq0 += __shfl_xor_sync(0xffffffffu, ysq0, 1);
        ysq0 += __shfl_xor_sync(0xffffffffu, ysq0, 2);
        ysq0 += __shfl_xor_sync(0xffffffffu, ysq0, 4);
        ysq1 += __shfl_xor_sync(0xffffffffu, ysq1, 1);
        ysq1 += __shfl_xor_sync(0xffffffffu, ysq1, 2);
        ysq1 += __shfl_xor_sync(0xffffffffu, ysq1, 4);
        if (o == 0) {
            g_ynp[ks][b * CDIM + j0 + tr]      = ysq0;
            g_ynp[ks][b * CDIM + j0 + tr + 64] = ysq1;
        }
    }

    // epilogue: streaming stores of packed bf16 partials (read-once data)
    const int gr = lane >> 2, gc = lane & 3;
    __nv_bfloat16* gout = g_part[ks];
#pragma unroll
    for (int mi = 0; mi < 2; ++mi) {
#pragma unroll
        for (int nb = 0; nb < 4; ++nb) {
            const int jc = j0w + nb * 8 + gc * 2;
            const int grow = b * CDIM + i0 + i0w + mi * 16 + gr;
            __stcs((uint32_t*)&gout[(size_t)grow * CDIM + j0 + jc],
                   bf2(acc[mi][nb][0], acc[mi][nb][1]));
            __stcs((uint32_t*)&gout[(size_t)(grow + 8) * CDIM + j0 + jc],
                   bf2(acc[mi][nb][2], acc[mi][nb][3]));
        }
    }
}

// ---------------------------------------------------------------------------
// 2) fused: argmin of (yn[j] - 2*dot) + exact-fp32 rescue + row gather.
//    Streaming loads on read-once partials; streaming stores on out so Y
//    stays L2-resident for the gather reads.
// ---------------------------------------------------------------------------
__global__ void __launch_bounds__(256) rescore_gather_kernel(const float* __restrict__ X,
                                                             const float* __restrict__ Y,
                                                             float* __restrict__ out) {
    const int row = blockIdx.x;           // b*CDIM + i
    const int b   = row >> 8;
    const int t   = threadIdx.x;

    __shared__ float s_red[8];
    __shared__ float s_minv;
    __shared__ int   s_cnt;
    __shared__ int   s_lst[256];
    __shared__ int   s_bestj;

    const size_t off = (size_t)row * CDIM + t;
    float dot = 0.f, yn = 0.f;
#pragma unroll
    for (int k = 0; k < KSPLIT; ++k) {
        uint16_t raw = __ldcs((const uint16_t*)&g_part[k][off]);
        dot += __bfloat162float(*reinterpret_cast<__nv_bfloat16*>(&raw));
        yn  += g_ynp[k][b * CDIM + t];
    }
    float d = yn - 2.f * dot;

    float vv = d;
#pragma unroll
    for (int o = 16; o; o >>= 1) vv = fminf(vv, __shfl_down_sync(0xffffffffu, vv, o));
    if ((t & 31) == 0) s_red[t >> 5] = vv;
    __syncthreads();
    if (t == 0) {
        float m = s_red[0];
#pragma unroll
        for (int i = 1; i < 8; ++i) m = fminf(m, s_red[i]);
        s_minv = m;
        s_cnt = 0;
    }
    __syncthreads();

    if (d <= s_minv + TAU) {
        int pos = atomicAdd(&s_cnt, 1);
        s_lst[pos] = t;
    }
    __syncthreads();

    const int n = s_cnt;
    if (n == 1) {
        if (t == 0) s_bestj = s_lst[0];
    } else {
        // exact fp32 rescore; tie -> lower j
        const float* xr = X + (size_t)row * HW;
        float bestv = 3.4e38f;
        int   bestj = 0x7fffffff;
        for (int c = 0; c < n; ++c) {
            const int j = s_lst[c];
            const float* yr = Y + (size_t)(b * CDIM + j) * HW;
            float s = 0.f;
#pragma unroll
            for (int q = 0; q < 4; ++q) {
                float4 xv = ((const float4*)xr)[t + q * 256];
                float4 yv = ((const float4*)yr)[t + q * 256];
                float dx = xv.x - yv.x, dy = xv.y - yv.y, dz = xv.z - yv.z, dw = xv.w - yv.w;
                s += dx * dx + dy * dy + dz * dz + dw * dw;
            }
#pragma unroll
            for (int o = 16; o; o >>= 1) s += __shfl_down_sync(0xffffffffu, s, o);
            if ((t & 31) == 0) s_red[t >> 5] = s;
            __syncthreads();
            if (t == 0) {
                float tot = 0.f;
#pragma unroll
                for (int i = 0; i < 8; ++i) tot += s_red[i];
                if (tot < bestv || (tot == bestv && j < bestj)) { bestv = tot; bestj = j; }
            }
            __syncthreads();
        }
        if (t == 0) s_bestj = bestj;
    }
    __syncthreads();

    // gather: copy Y[b, bestj, :] -> out[row, :] with streaming stores
    const float4* yp = (const float4*)(Y + (size_t)(b * CDIM + s_bestj) * HW);
    float4*       op = (float4*)(out + (size_t)row * HW);
#pragma unroll
    for (int q = 0; q < 4; ++q) {
        float4 v = yp[t + q * 256];
        __stcs(&op[t + q * 256], v);
    }
}

// ---------------------------------------------------------------------------
extern "C" void kernel_launch(void* const* d_in, const int* in_sizes, int n_in,
                              void* d_out, int out_size) {
    const float* x = (const float*)d_in[0];
    const float* y = (const float*)d_in[1];
    float* out = (float*)d_out;

    cudaFuncSetAttribute(gemm_kernel,
                         cudaFuncAttributeMaxDynamicSharedMemorySize, SMEM_BYTES);

    dim3 g(CDIM / 128, CDIM / 128, BATCH * KSPLIT);   // 2 x 2 x 128 = 512 CTAs
    gemm_kernel<<<g, 512, SMEM_BYTES>>>(x, y);

    rescore_gather_kernel<<<BATCH * CDIM, 256>>>(x, y, out);
}